// round 13
// baseline (speedup 1.0000x reference)
#include <cuda_runtime.h>
#include <math.h>
#include <stdint.h>

#define S_LEN 577
#define BATCH 8
#define DIM   1024
#define NHEAD 16
#define HD    64
#define NBOX  16
#define NROWS (S_LEN*BATCH)   /* 4616 */
#define MROW  136             /* 128 mask rows + 8 cls rows */

/* ------------------------------------------------------------------ */
/* scratch (device globals; no allocation allowed)                    */
/* ------------------------------------------------------------------ */
__device__ float g_h[NROWS*DIM];          // LN1 output (tf32-rounded)
__device__ float g_kv[NROWS*2048];        // [row, 0:1024]=k, [1024:2048]=v
__device__ float g_attn[BATCH*NHEAD*S_LEN];
__device__ float g_attout[MROW*DIM];      // tf32-rounded
__device__ float g_resid[MROW*DIM];
__device__ float g_t[MROW*DIM];           // tf32-rounded
__device__ float g_fc[MROW*4096];         // tf32-rounded
__device__ float g_part[4*MROW*4096];     // split-K partials (= 16*MROW*1024)

/* ------------------------------------------------------------------ */
__device__ __forceinline__ float block_reduce(float v, float* sm, bool is_max) {
    int lane = threadIdx.x & 31, wid = threadIdx.x >> 5;
    #pragma unroll
    for (int o = 16; o; o >>= 1) {
        float u = __shfl_down_sync(0xffffffffu, v, o);
        v = is_max ? fmaxf(v, u) : v + u;
    }
    if (lane == 0) sm[wid] = v;
    __syncthreads();
    int nw = blockDim.x >> 5;
    if (wid == 0) {
        v = (lane < nw) ? sm[lane] : (is_max ? -3.0e38f : 0.0f);
        #pragma unroll
        for (int o = 16; o; o >>= 1) {
            float u = __shfl_down_sync(0xffffffffu, v, o);
            v = is_max ? fmaxf(v, u) : v + u;
        }
        if (lane == 0) sm[0] = v;
    }
    __syncthreads();
    float r = sm[0];
    __syncthreads();
    return r;
}

__device__ __forceinline__ float f2tf32f(float f) {
    uint32_t u;
    asm("cvt.rna.tf32.f32 %0, %1;" : "=r"(u) : "f"(f));
    return __uint_as_float(u);
}

__device__ __forceinline__ void cp_async16(uint32_t saddr, const void* gaddr, int src_size) {
    asm volatile("cp.async.cg.shared.global [%0], [%1], 16, %2;\n"
                 :: "r"(saddr), "l"(gaddr), "r"(src_size));
}

__device__ __forceinline__ uint32_t smem_u32(const void* p) {
    return (uint32_t)__cvta_generic_to_shared(p);
}

/* ------------------------------------------------------------------ */
/* LayerNorm over 1024 cols, one block (256 thr) per row. out tf32.   */
/* ------------------------------------------------------------------ */
__global__ void ln1_kernel(const float* __restrict__ x,
                           const float* __restrict__ g,
                           const float* __restrict__ b,
                           float* __restrict__ out) {
    __shared__ float sred[32];
    int row = blockIdx.x, t = threadIdx.x;
    float4 v = ((const float4*)(x + (size_t)row*DIM))[t];
    float s = v.x + v.y + v.z + v.w;
    s = block_reduce(s, sred, false);
    float mean = s * (1.0f/DIM);
    float dx = v.x-mean, dy = v.y-mean, dz = v.z-mean, dw = v.w-mean;
    float ss = dx*dx + dy*dy + dz*dz + dw*dw;
    ss = block_reduce(ss, sred, false);
    float inv = rsqrtf(ss*(1.0f/DIM) + 1e-5f);
    float4 gv = ((const float4*)g)[t];
    float4 bv = ((const float4*)b)[t];
    float4 o;
    o.x = f2tf32f(dx*inv*gv.x + bv.x);  o.y = f2tf32f(dy*inv*gv.y + bv.y);
    o.z = f2tf32f(dz*inv*gv.z + bv.z);  o.w = f2tf32f(dw*inv*gv.w + bv.w);
    ((float4*)(out + (size_t)row*DIM))[t] = o;
}

/* ------------------------------------------------------------------ */
/* tf32 GEMM: 128 threads, BM=BN=128, BK=32, warp tile 64x64,         */
/* cp.async double-buffered, 2 CTA/SM. SPLITK>1: partials, no bias.   */
/* ------------------------------------------------------------------ */
#define TSTRIDE 36
#define TILE_F (128*TSTRIDE)
#define GEMM_SMEM (2*2*TILE_F*4)   /* 73728 B */

template<int ACT, int RND, int SPLITK>
__global__ void __launch_bounds__(128, 2)
gemm_w64(const float* __restrict__ A,
         const float* __restrict__ W,
         const float* __restrict__ bias,
         float* __restrict__ C,
         int M, int N, int K) {
    extern __shared__ float smemf[];
    float* Abuf = smemf;
    float* Bbuf = smemf + 2*TILE_F;
    uint32_t Abase = smem_u32(Abuf);
    uint32_t Bbase = smem_u32(Bbuf);

    int tid = threadIdx.x;
    int warp = tid >> 5, lane = tid & 31;
    int wm = warp & 1, wn = warp >> 1;
    int g = lane >> 2, c = lane & 3;
    int m0 = blockIdx.y * 128, n0 = blockIdx.x * 128;
    int Kc = K / SPLITK;
    int kbase = blockIdx.z * Kc;

    float acc[4][8][4];
    #pragma unroll
    for (int i = 0; i < 4; i++)
        #pragma unroll
        for (int j = 0; j < 8; j++)
            #pragma unroll
            for (int r = 0; r < 4; r++) acc[i][j][r] = 0.0f;

    const int NIT = Kc >> 5;

    auto load_tile = [&](int s, int k0) {
        #pragma unroll
        for (int i = 0; i < 8; i++) {
            int ch = tid + i*128;
            int m = ch >> 3, kq = ch & 7;
            const float* ga = A + (size_t)(m0 + m)*K + k0 + kq*4;
            int sz = (m0 + m < M) ? 16 : 0;
            cp_async16(Abase + (uint32_t)((s*TILE_F + m*TSTRIDE + kq*4)*4), ga, sz);
            const float* gb = W + (size_t)(n0 + m)*K + k0 + kq*4;
            cp_async16(Bbase + (uint32_t)((s*TILE_F + m*TSTRIDE + kq*4)*4), gb, 16);
        }
    };

    load_tile(0, kbase);
    asm volatile("cp.async.commit_group;\n");

    int buf = 0;
    for (int it = 0; it < NIT; it++) {
        if (it + 1 < NIT) load_tile(buf ^ 1, kbase + ((it + 1) << 5));
        asm volatile("cp.async.commit_group;\n");
        asm volatile("cp.async.wait_group 1;\n");
        __syncthreads();

        const float* As_s = Abuf + buf*TILE_F;
        const float* Bs_s = Bbuf + buf*TILE_F;
        #pragma unroll
        for (int kk = 0; kk < 32; kk += 8) {
            uint32_t a[4][4];
            #pragma unroll
            for (int i = 0; i < 4; i++) {
                int mr = (wm*64 + i*16 + g) * TSTRIDE;
                a[i][0] = __float_as_uint(As_s[mr             + kk + c    ]);
                a[i][1] = __float_as_uint(As_s[mr + 8*TSTRIDE + kk + c    ]);
                a[i][2] = __float_as_uint(As_s[mr             + kk + c + 4]);
                a[i][3] = __float_as_uint(As_s[mr + 8*TSTRIDE + kk + c + 4]);
            }
            uint32_t b[8][2];
            #pragma unroll
            for (int j = 0; j < 8; j++) {
                int nc = (wn*64 + j*8 + g) * TSTRIDE;
                b[j][0] = __float_as_uint(Bs_s[nc + kk + c    ]);
                b[j][1] = __float_as_uint(Bs_s[nc + kk + c + 4]);
            }
            #pragma unroll
            for (int i = 0; i < 4; i++)
                #pragma unroll
                for (int j = 0; j < 8; j++) {
                    asm volatile(
                        "mma.sync.aligned.m16n8k8.row.col.f32.tf32.tf32.f32 "
                        "{%0,%1,%2,%3}, {%4,%5,%6,%7}, {%8,%9}, {%0,%1,%2,%3};\n"
                        : "+f"(acc[i][j][0]), "+f"(acc[i][j][1]),
                          "+f"(acc[i][j][2]), "+f"(acc[i][j][3])
                        : "r"(a[i][0]), "r"(a[i][1]), "r"(a[i][2]), "r"(a[i][3]),
                          "r"(b[j][0]), "r"(b[j][1]));
                }
        }
        __syncthreads();
        buf ^= 1;
    }

    float* Co = (SPLITK > 1) ? (C + (size_t)blockIdx.z * M * N) : C;
    #pragma unroll
    for (int i = 0; i < 4; i++) {
        int mA = m0 + wm*64 + i*16 + g;
        int mB = mA + 8;
        #pragma unroll
        for (int j = 0; j < 8; j++) {
            int n = n0 + wn*64 + j*8 + 2*c;
            float b0 = 0.0f, b1 = 0.0f;
            if (SPLITK == 1) { b0 = bias[n]; b1 = bias[n+1]; }
            if (mA < M) {
                float v0 = acc[i][j][0] + b0;
                float v1 = acc[i][j][1] + b1;
                if (ACT == 1) {
                    v0 = v0 / (1.0f + expf(-1.702f * v0));
                    v1 = v1 / (1.0f + expf(-1.702f * v1));
                }
                if (RND == 1) { v0 = f2tf32f(v0); v1 = f2tf32f(v1); }
                *(float2*)(Co + (size_t)mA*N + n) = make_float2(v0, v1);
            }
            if (mB < M) {
                float v0 = acc[i][j][2] + b0;
                float v1 = acc[i][j][3] + b1;
                if (ACT == 1) {
                    v0 = v0 / (1.0f + expf(-1.702f * v0));
                    v1 = v1 / (1.0f + expf(-1.702f * v1));
                }
                if (RND == 1) { v0 = f2tf32f(v0); v1 = f2tf32f(v1); }
                *(float2*)(Co + (size_t)mB*N + n) = make_float2(v0, v1);
            }
        }
    }
}

/* ------------------------------------------------------------------ */
/* attn logits per (b,h): q proj + q.K -> g_attn. 256 threads.        */
/* ------------------------------------------------------------------ */
__global__ void attn_logits_kernel(const float* __restrict__ wq,
                                   const float* __restrict__ bq) {
    __shared__ float sm_h[DIM];
    __shared__ float sm_q[HD];
    int bh = blockIdx.x, b = bh >> 4, h = bh & 15;
    int t = threadIdx.x;               // 256
    int warp = t >> 5, lane = t & 31;

    ((float4*)sm_h)[t] = ((const float4*)(g_h + (size_t)b*DIM))[t];
    __syncthreads();

    /* q projection: warp w computes outputs e = w*8 .. w*8+7 */
    #pragma unroll
    for (int i = 0; i < 8; i++) {
        int e = warp*8 + i;
        const float4* wr = (const float4*)(wq + (size_t)(h*HD + e)*DIM);
        float acc = 0.0f;
        #pragma unroll
        for (int ii = 0; ii < 8; ii++) {
            float4 a = ((const float4*)sm_h)[lane + ii*32];
            float4 w4 = wr[lane + ii*32];
            acc += a.x*w4.x + a.y*w4.y + a.z*w4.z + a.w*w4.w;
        }
        #pragma unroll
        for (int o = 16; o; o >>= 1) acc += __shfl_down_sync(0xffffffffu, acc, o);
        if (lane == 0) sm_q[e] = (acc + bq[h*HD + e]) * 0.125f;
    }
    __syncthreads();

    for (int s = t; s < S_LEN; s += 256) {
        const float4* kr = (const float4*)(g_kv + (size_t)(s*BATCH + b)*2048 + h*HD);
        float acc = 0.0f;
        #pragma unroll
        for (int i = 0; i < 16; i++) {
            float4 kv4 = kr[i];
            acc += kv4.x*sm_q[i*4+0] + kv4.y*sm_q[i*4+1]
                 + kv4.z*sm_q[i*4+2] + kv4.w*sm_q[i*4+3];
        }
        g_attn[bh*S_LEN + s] = acc;
    }
}

/* ------------------------------------------------------------------ */
/* softmax (NV variants from VBASE) + P@V per (b,h). 512 threads,     */
/* 2 blocks/SM. P@V split 8 ways over s with smem tree reduce.        */
/* smem floats: p NV*577 | attn 580 | part NV*512                     */
/* ------------------------------------------------------------------ */
template<int NV, int VBASE>
__global__ void __launch_bounds__(512, 2)
softmax_pv_kernel(const float* __restrict__ mask) {
    extern __shared__ float sm[];
    float* sm_p    = sm;                    // NV*577
    float* sm_attn = sm + NV*S_LEN;         // 577 (pad 580)
    float* sm_part = sm + NV*S_LEN + 580;   // 8*NV*64
    int bh = blockIdx.x, b = bh >> 4, h = bh & 15;
    int t = threadIdx.x;               // 512
    int warp = t >> 5, lane = t & 31;

    for (int s = t; s < S_LEN; s += 512) sm_attn[s] = g_attn[bh*S_LEN + s];
    __syncthreads();

    /* softmax, warp-per-variant (16 warps for NV<=9 -> 1 iter) */
    for (int iv = warp; iv < NV; iv += 16) {
        int var = VBASE + iv;
        float* pr = sm_p + iv * S_LEN;
        const float* mrow = (var < 16)
            ? (mask + (size_t)((b*NBOX + var)*NHEAD + h) * S_LEN) : (const float*)0;
        float mx = -3.0e38f;
        for (int s = lane; s < S_LEN; s += 32) {
            float a = sm_attn[s] + (mrow ? __ldg(mrow + s) : 0.0f);
            pr[s] = a;
            mx = fmaxf(mx, a);
        }
        #pragma unroll
        for (int o = 16; o; o >>= 1)
            mx = fmaxf(mx, __shfl_xor_sync(0xffffffffu, mx, o));
        float sum = 0.0f;
        for (int s = lane; s < S_LEN; s += 32) {
            float e = expf(pr[s] - mx);
            pr[s] = e;
            sum += e;
        }
        #pragma unroll
        for (int o = 16; o; o >>= 1)
            sum += __shfl_xor_sync(0xffffffffu, sum, o);
        float inv = 1.0f / sum;
        for (int s = lane; s < S_LEN; s += 32) pr[s] *= inv;
    }
    __syncthreads();

    /* P @ V: thread (e, rg) accumulates NV variants over s = rg mod 8 */
    {
        int e = t & 63, rg = t >> 6;
        const float* vcol = g_kv + 1024 + h*HD + e;
        float acc[NV];
        #pragma unroll
        for (int v = 0; v < NV; v++) acc[v] = 0.0f;

        float vv = vcol[(size_t)(rg*BATCH + b)*2048];
        for (int s = rg; s < S_LEN; s += 8) {
            float vcur = vv;
            int sn = s + 8;
            vv = (sn < S_LEN) ? vcol[(size_t)(sn*BATCH + b)*2048] : 0.0f;
            #pragma unroll
            for (int v = 0; v < NV; v++)
                acc[v] += sm_p[v*S_LEN + s] * vcur;
        }
        #pragma unroll
        for (int v = 0; v < NV; v++)
            sm_part[rg*(NV*64) + v*64 + e] = acc[v];
    }
    __syncthreads();

    /* reduce 8 rg-partials -> NV*64 outputs */
    for (int o = t; o < NV*64; o += 512) {
        int var = VBASE + (o >> 6), e2 = o & 63;
        float s = 0.0f;
        #pragma unroll
        for (int rg = 0; rg < 8; rg++) s += sm_part[rg*(NV*64) + o];
        int col = h*HD + e2;
        if (var < 16)
            g_attout[(size_t)(b*NBOX + var)*DIM + col] = f2tf32f(s);
        else
            g_attout[(size_t)(128 + b)*DIM + col] = f2tf32f(s);
    }
}

#define PV_SMEM(NV) ((NV*S_LEN + 580 + NV*512)*4)

/* ------------------------------------------------------------------ */
__global__ void gelu_reduce_kernel(const float* __restrict__ fb) {
    int i = blockIdx.x * blockDim.x + threadIdx.x;
    if (i >= MROW*4096/4) return;
    int n4 = i & (4096/4 - 1);
    float4 bv = ((const float4*)fb)[n4];
    float v[4] = {bv.x, bv.y, bv.z, bv.w};
    #pragma unroll
    for (int z = 0; z < 4; z++) {
        float4 p = ((const float4*)g_part)[(size_t)z*(MROW*4096/4) + i];
        v[0] += p.x; v[1] += p.y; v[2] += p.z; v[3] += p.w;
    }
    float4 o;
    #pragma unroll
    for (int j = 0; j < 4; j++)
        v[j] = f2tf32f(v[j] / (1.0f + expf(-1.702f * v[j])));
    o.x = v[0]; o.y = v[1]; o.z = v[2]; o.w = v[3];
    ((float4*)g_fc)[i] = o;
}

/* ------------------------------------------------------------------ */
__global__ void resid_ln2_kernel(const float* __restrict__ x,
                                 const float* __restrict__ ob,
                                 const float* __restrict__ g2,
                                 const float* __restrict__ b2) {
    __shared__ float sred[32];
    int m = blockIdx.x, t = threadIdx.x;
    int b = (m < 128) ? (m >> 4) : (m - 128);
    float4 xv = ((const float4*)(x + (size_t)b*DIM))[t];
    float4 bo = ((const float4*)ob)[t];
    float rx = xv.x + bo.x, ry = xv.y + bo.y, rz = xv.z + bo.z, rw = xv.w + bo.w;
    #pragma unroll
    for (int z = 0; z < 8; z++) {
        float4 p = ((const float4*)(g_part + (size_t)(z*MROW + m)*DIM))[t];
        rx += p.x; ry += p.y; rz += p.z; rw += p.w;
    }
    float4 r = make_float4(rx, ry, rz, rw);
    ((float4*)(g_resid + (size_t)m*DIM))[t] = r;
    float s = r.x + r.y + r.z + r.w;
    s = block_reduce(s, sred, false);
    float mean = s * (1.0f/DIM);
    float dx = r.x-mean, dy = r.y-mean, dz = r.z-mean, dw = r.w-mean;
    float ss = dx*dx + dy*dy + dz*dz + dw*dw;
    ss = block_reduce(ss, sred, false);
    float inv = rsqrtf(ss*(1.0f/DIM) + 1e-5f);
    float4 gv = ((const float4*)g2)[t];
    float4 bv = ((const float4*)b2)[t];
    float4 o;
    o.x = f2tf32f(dx*inv*gv.x + bv.x);  o.y = f2tf32f(dy*inv*gv.y + bv.y);
    o.z = f2tf32f(dz*inv*gv.z + bv.z);  o.w = f2tf32f(dw*inv*gv.w + bv.w);
    ((float4*)(g_t + (size_t)m*DIM))[t] = o;
}

/* ------------------------------------------------------------------ */
__global__ void final_kernel(const float* __restrict__ pb, float* __restrict__ out) {
    int m = blockIdx.x, t = threadIdx.x;
    float4 r  = ((const float4*)(g_resid + (size_t)m*DIM))[t];
    float4 bv = ((const float4*)pb)[t];
    float ox = r.x + bv.x, oy = r.y + bv.y, oz = r.z + bv.z, ow = r.w + bv.w;
    #pragma unroll
    for (int z = 0; z < 16; z++) {
        float4 p = ((const float4*)(g_part + (size_t)(z*MROW + m)*DIM))[t];
        ox += p.x; oy += p.y; oz += p.z; ow += p.w;
    }
    float4 o = make_float4(ox, oy, oz, ow);
    float* dst = (m < 128) ? (out + (size_t)m*DIM)
                           : (out + 128*DIM + (size_t)(m-128)*DIM);
    ((float4*)dst)[t] = o;
}

/* ------------------------------------------------------------------ */
extern "C" void kernel_launch(void* const* d_in, const int* in_sizes, int n_in,
                              void* d_out, int out_size) {
    const float* x         = (const float*)d_in[0];
    const float* mask      = (const float*)d_in[1];
    const float* in_proj_w = (const float*)d_in[5];
    const float* in_proj_b = (const float*)d_in[6];
    const float* out_w     = (const float*)d_in[7];
    const float* out_b     = (const float*)d_in[8];
    const float* ln1_g     = (const float*)d_in[9];
    const float* ln1_b     = (const float*)d_in[10];
    const float* ln2_g     = (const float*)d_in[11];
    const float* ln2_b     = (const float*)d_in[12];
    const float* fc_w      = (const float*)d_in[13];
    const float* fc_b      = (const float*)d_in[14];
    const float* proj_w    = (const float*)d_in[15];
    const float* proj_b    = (const float*)d_in[16];

    float *ph, *pkv, *pattout, *pt, *pfc, *ppart;
    cudaGetSymbolAddress((void**)&ph,      g_h);
    cudaGetSymbolAddress((void**)&pkv,     g_kv);
    cudaGetSymbolAddress((void**)&pattout, g_attout);
    cudaGetSymbolAddress((void**)&pt,      g_t);
    cudaGetSymbolAddress((void**)&pfc,     g_fc);
    cudaGetSymbolAddress((void**)&ppart,   g_part);

    cudaFuncSetAttribute(gemm_w64<0,0,1>,  cudaFuncAttributeMaxDynamicSharedMemorySize, GEMM_SMEM);
    cudaFuncSetAttribute(gemm_w64<0,0,4>,  cudaFuncAttributeMaxDynamicSharedMemorySize, GEMM_SMEM);
    cudaFuncSetAttribute(gemm_w64<0,0,8>,  cudaFuncAttributeMaxDynamicSharedMemorySize, GEMM_SMEM);
    cudaFuncSetAttribute(gemm_w64<0,0,16>, cudaFuncAttributeMaxDynamicSharedMemorySize, GEMM_SMEM);
    cudaFuncSetAttribute((const void*)softmax_pv_kernel<8,0>,
                         cudaFuncAttributeMaxDynamicSharedMemorySize, PV_SMEM(8));
    cudaFuncSetAttribute((const void*)softmax_pv_kernel<9,8>,
                         cudaFuncAttributeMaxDynamicSharedMemorySize, PV_SMEM(9));

    /* 1. LN1 over all tokens (tf32-rounded out) */
    ln1_kernel<<<NROWS, 256>>>(x, ln1_g, ln1_b, ph);

    /* 2. K,V projection: [4616,1024] x [2048,1024]^T (tf32 path) */
    gemm_w64<0,0,1><<<dim3(2048/128, (NROWS+127)/128), 128, GEMM_SMEM>>>(
        ph, in_proj_w + 1024*1024, in_proj_b + 1024, pkv, NROWS, 2048, 1024);

    /* 3. q proj + attn logits (once per (b,h)) */
    attn_logits_kernel<<<BATCH*NHEAD, 256>>>(in_proj_w, in_proj_b);

    /* 4-5. softmax + P@V, variants split across two launches, 2 blk/SM */
    softmax_pv_kernel<8,0><<<BATCH*NHEAD, 512, PV_SMEM(8)>>>(mask);
    softmax_pv_kernel<9,8><<<BATCH*NHEAD, 512, PV_SMEM(9)>>>(mask);

    /* 6. output projection, split-K 8 (128 CTAs) */
    gemm_w64<0,0,8><<<dim3(1024/128, 2, 8), 128, GEMM_SMEM>>>(
        pattout, out_w, out_b, ppart, MROW, 1024, 1024);

    /* 7. residual + out_b + LN2 (reduces 8 partials) */
    resid_ln2_kernel<<<MROW, 256>>>(x, out_b, ln2_g, ln2_b);

    /* 8. MLP fc, split-K 4 (256 CTAs) */
    gemm_w64<0,0,4><<<dim3(4096/128, 2, 4), 128, GEMM_SMEM>>>(
        pt, fc_w, fc_b, ppart, MROW, 4096, 1024);

    /* 9. reduce 4 partials + bias + QuickGELU */
    gelu_reduce_kernel<<<(MROW*4096/4 + 255)/256, 256>>>(fc_b);

    /* 10. MLP proj, split-K 16 (256 CTAs) */
    gemm_w64<0,0,16><<<dim3(1024/128, 2, 16), 128, GEMM_SMEM>>>(
        pfc, proj_w, proj_b, ppart, MROW, 1024, 4096);

    /* 11. residual + proj_b + scatter (reduces 16 partials) */
    final_kernel<<<MROW, 256>>>(proj_b, (float*)d_out);
}

// round 14
// speedup vs baseline: 1.1431x; 1.1431x over previous
#include <cuda_runtime.h>
#include <math.h>
#include <stdint.h>

#define S_LEN 577
#define BATCH 8
#define DIM   1024
#define NHEAD 16
#define HD    64
#define NBOX  16
#define NROWS (S_LEN*BATCH)   /* 4616 */
#define MROW  136             /* 128 mask rows + 8 cls rows */

#define PROW 608              /* padded p-row (multiple of 4, >= 8*76) */
#define CHUNK 76              /* s-chunk per rg group */

/* ------------------------------------------------------------------ */
/* scratch (device globals; no allocation allowed)                    */
/* ------------------------------------------------------------------ */
__device__ float g_h[NROWS*DIM];          // LN1 output (tf32-rounded)
__device__ float g_kv[NROWS*2048];        // [row, 0:1024]=k, [1024:2048]=v
__device__ float g_attout[MROW*DIM];      // tf32-rounded
__device__ float g_resid[MROW*DIM];
__device__ float g_t[MROW*DIM];           // tf32-rounded
__device__ float g_fc[MROW*4096];         // tf32-rounded
__device__ float g_part[4*MROW*4096];     // split-K partials (= 16*MROW*1024)

/* ------------------------------------------------------------------ */
__device__ __forceinline__ float block_reduce(float v, float* sm, bool is_max) {
    int lane = threadIdx.x & 31, wid = threadIdx.x >> 5;
    #pragma unroll
    for (int o = 16; o; o >>= 1) {
        float u = __shfl_down_sync(0xffffffffu, v, o);
        v = is_max ? fmaxf(v, u) : v + u;
    }
    if (lane == 0) sm[wid] = v;
    __syncthreads();
    int nw = blockDim.x >> 5;
    if (wid == 0) {
        v = (lane < nw) ? sm[lane] : (is_max ? -3.0e38f : 0.0f);
        #pragma unroll
        for (int o = 16; o; o >>= 1) {
            float u = __shfl_down_sync(0xffffffffu, v, o);
            v = is_max ? fmaxf(v, u) : v + u;
        }
        if (lane == 0) sm[0] = v;
    }
    __syncthreads();
    float r = sm[0];
    __syncthreads();
    return r;
}

__device__ __forceinline__ float f2tf32f(float f) {
    uint32_t u;
    asm("cvt.rna.tf32.f32 %0, %1;" : "=r"(u) : "f"(f));
    return __uint_as_float(u);
}

__device__ __forceinline__ void cp_async16(uint32_t saddr, const void* gaddr, int src_size) {
    asm volatile("cp.async.cg.shared.global [%0], [%1], 16, %2;\n"
                 :: "r"(saddr), "l"(gaddr), "r"(src_size));
}

__device__ __forceinline__ uint32_t smem_u32(const void* p) {
    return (uint32_t)__cvta_generic_to_shared(p);
}

/* ------------------------------------------------------------------ */
/* LayerNorm over 1024 cols, one block (256 thr) per row. out tf32.   */
/* ------------------------------------------------------------------ */
__global__ void ln1_kernel(const float* __restrict__ x,
                           const float* __restrict__ g,
                           const float* __restrict__ b,
                           float* __restrict__ out) {
    __shared__ float sred[32];
    int row = blockIdx.x, t = threadIdx.x;
    float4 v = ((const float4*)(x + (size_t)row*DIM))[t];
    float s = v.x + v.y + v.z + v.w;
    s = block_reduce(s, sred, false);
    float mean = s * (1.0f/DIM);
    float dx = v.x-mean, dy = v.y-mean, dz = v.z-mean, dw = v.w-mean;
    float ss = dx*dx + dy*dy + dz*dz + dw*dw;
    ss = block_reduce(ss, sred, false);
    float inv = rsqrtf(ss*(1.0f/DIM) + 1e-5f);
    float4 gv = ((const float4*)g)[t];
    float4 bv = ((const float4*)b)[t];
    float4 o;
    o.x = f2tf32f(dx*inv*gv.x + bv.x);  o.y = f2tf32f(dy*inv*gv.y + bv.y);
    o.z = f2tf32f(dz*inv*gv.z + bv.z);  o.w = f2tf32f(dw*inv*gv.w + bv.w);
    ((float4*)(out + (size_t)row*DIM))[t] = o;
}

/* ------------------------------------------------------------------ */
/* tf32 GEMM: 128 threads, BM=BN=128, BK=32, warp tile 64x64,         */
/* cp.async double-buffered, 2 CTA/SM. SPLITK>1: partials, no bias.   */
/* ------------------------------------------------------------------ */
#define TSTRIDE 36
#define TILE_F (128*TSTRIDE)
#define GEMM_SMEM (2*2*TILE_F*4)   /* 73728 B */

template<int ACT, int RND, int SPLITK>
__global__ void __launch_bounds__(128, 2)
gemm_w64(const float* __restrict__ A,
         const float* __restrict__ W,
         const float* __restrict__ bias,
         float* __restrict__ C,
         int M, int N, int K) {
    extern __shared__ float smemf[];
    float* Abuf = smemf;
    float* Bbuf = smemf + 2*TILE_F;
    uint32_t Abase = smem_u32(Abuf);
    uint32_t Bbase = smem_u32(Bbuf);

    int tid = threadIdx.x;
    int warp = tid >> 5, lane = tid & 31;
    int wm = warp & 1, wn = warp >> 1;
    int g = lane >> 2, c = lane & 3;
    int m0 = blockIdx.y * 128, n0 = blockIdx.x * 128;
    int Kc = K / SPLITK;
    int kbase = blockIdx.z * Kc;

    float acc[4][8][4];
    #pragma unroll
    for (int i = 0; i < 4; i++)
        #pragma unroll
        for (int j = 0; j < 8; j++)
            #pragma unroll
            for (int r = 0; r < 4; r++) acc[i][j][r] = 0.0f;

    const int NIT = Kc >> 5;

    auto load_tile = [&](int s, int k0) {
        #pragma unroll
        for (int i = 0; i < 8; i++) {
            int ch = tid + i*128;
            int m = ch >> 3, kq = ch & 7;
            const float* ga = A + (size_t)(m0 + m)*K + k0 + kq*4;
            int sz = (m0 + m < M) ? 16 : 0;
            cp_async16(Abase + (uint32_t)((s*TILE_F + m*TSTRIDE + kq*4)*4), ga, sz);
            const float* gb = W + (size_t)(n0 + m)*K + k0 + kq*4;
            cp_async16(Bbase + (uint32_t)((s*TILE_F + m*TSTRIDE + kq*4)*4), gb, 16);
        }
    };

    load_tile(0, kbase);
    asm volatile("cp.async.commit_group;\n");

    int buf = 0;
    for (int it = 0; it < NIT; it++) {
        if (it + 1 < NIT) load_tile(buf ^ 1, kbase + ((it + 1) << 5));
        asm volatile("cp.async.commit_group;\n");
        asm volatile("cp.async.wait_group 1;\n");
        __syncthreads();

        const float* As_s = Abuf + buf*TILE_F;
        const float* Bs_s = Bbuf + buf*TILE_F;
        #pragma unroll
        for (int kk = 0; kk < 32; kk += 8) {
            uint32_t a[4][4];
            #pragma unroll
            for (int i = 0; i < 4; i++) {
                int mr = (wm*64 + i*16 + g) * TSTRIDE;
                a[i][0] = __float_as_uint(As_s[mr             + kk + c    ]);
                a[i][1] = __float_as_uint(As_s[mr + 8*TSTRIDE + kk + c    ]);
                a[i][2] = __float_as_uint(As_s[mr             + kk + c + 4]);
                a[i][3] = __float_as_uint(As_s[mr + 8*TSTRIDE + kk + c + 4]);
            }
            uint32_t b[8][2];
            #pragma unroll
            for (int j = 0; j < 8; j++) {
                int nc = (wn*64 + j*8 + g) * TSTRIDE;
                b[j][0] = __float_as_uint(Bs_s[nc + kk + c    ]);
                b[j][1] = __float_as_uint(Bs_s[nc + kk + c + 4]);
            }
            #pragma unroll
            for (int i = 0; i < 4; i++)
                #pragma unroll
                for (int j = 0; j < 8; j++) {
                    asm volatile(
                        "mma.sync.aligned.m16n8k8.row.col.f32.tf32.tf32.f32 "
                        "{%0,%1,%2,%3}, {%4,%5,%6,%7}, {%8,%9}, {%0,%1,%2,%3};\n"
                        : "+f"(acc[i][j][0]), "+f"(acc[i][j][1]),
                          "+f"(acc[i][j][2]), "+f"(acc[i][j][3])
                        : "r"(a[i][0]), "r"(a[i][1]), "r"(a[i][2]), "r"(a[i][3]),
                          "r"(b[j][0]), "r"(b[j][1]));
                }
        }
        __syncthreads();
        buf ^= 1;
    }

    float* Co = (SPLITK > 1) ? (C + (size_t)blockIdx.z * M * N) : C;
    #pragma unroll
    for (int i = 0; i < 4; i++) {
        int mA = m0 + wm*64 + i*16 + g;
        int mB = mA + 8;
        #pragma unroll
        for (int j = 0; j < 8; j++) {
            int n = n0 + wn*64 + j*8 + 2*c;
            float b0 = 0.0f, b1 = 0.0f;
            if (SPLITK == 1) { b0 = bias[n]; b1 = bias[n+1]; }
            if (mA < M) {
                float v0 = acc[i][j][0] + b0;
                float v1 = acc[i][j][1] + b1;
                if (ACT == 1) {
                    v0 = v0 / (1.0f + expf(-1.702f * v0));
                    v1 = v1 / (1.0f + expf(-1.702f * v1));
                }
                if (RND == 1) { v0 = f2tf32f(v0); v1 = f2tf32f(v1); }
                *(float2*)(Co + (size_t)mA*N + n) = make_float2(v0, v1);
            }
            if (mB < M) {
                float v0 = acc[i][j][2] + b0;
                float v1 = acc[i][j][3] + b1;
                if (ACT == 1) {
                    v0 = v0 / (1.0f + expf(-1.702f * v0));
                    v1 = v1 / (1.0f + expf(-1.702f * v1));
                }
                if (RND == 1) { v0 = f2tf32f(v0); v1 = f2tf32f(v1); }
                *(float2*)(Co + (size_t)mB*N + n) = make_float2(v0, v1);
            }
        }
    }
}

/* ------------------------------------------------------------------ */
/* Fused attention per (b,h), 512 threads (round-10 structure):       */
/*   q proj + attn logits + 17 softmax (warp-per-variant) +           */
/*   P@V with CONTIGUOUS 76-wide s-chunks + float4 LDS on p rows.     */
/* smem floats: p 17*608=10336 | attn 580 | h 1024 | q 64 |           */
/*              part 8704  => 20708 floats = 82832 B                  */
/* ------------------------------------------------------------------ */
#define ATT_SMEM (20708*4)

__global__ void __launch_bounds__(512, 1)
fused_attn_kernel(const float* __restrict__ mask,
                  const float* __restrict__ wq,
                  const float* __restrict__ bq) {
    extern __shared__ float sm[];
    float* sm_p    = sm;               // 17*608 (padded rows)
    float* sm_attn = sm + 10336;       // 577 (pad 580)
    float* sm_h    = sm + 10916;       // 1024
    float* sm_q    = sm + 11940;       // 64
    float* sm_part = sm + 12004;       // 8*17*64
    int bh = blockIdx.x, b = bh >> 4, h = bh & 15;
    int t = threadIdx.x;               // 512
    int warp = t >> 5, lane = t & 31;

    /* load LN1(x[0,b]) row */
    if (t < 256) ((float4*)sm_h)[t] = ((const float4*)(g_h + (size_t)b*DIM))[t];
    __syncthreads();

    /* q projection: warp w computes outputs e = w*4 .. w*4+3 */
    #pragma unroll
    for (int i = 0; i < 4; i++) {
        int e = warp*4 + i;
        const float4* wr = (const float4*)(wq + (size_t)(h*HD + e)*DIM);
        float acc = 0.0f;
        #pragma unroll
        for (int ii = 0; ii < 8; ii++) {
            float4 a = ((const float4*)sm_h)[lane + ii*32];
            float4 w4 = wr[lane + ii*32];
            acc += a.x*w4.x + a.y*w4.y + a.z*w4.z + a.w*w4.w;
        }
        #pragma unroll
        for (int o = 16; o; o >>= 1) acc += __shfl_down_sync(0xffffffffu, acc, o);
        if (lane == 0) sm_q[e] = (acc + bq[h*HD + e]) * 0.125f;
    }
    __syncthreads();

    /* attn logits */
    for (int s = t; s < S_LEN; s += 512) {
        const float4* kr = (const float4*)(g_kv + (size_t)(s*BATCH + b)*2048 + h*HD);
        float acc = 0.0f;
        #pragma unroll
        for (int i = 0; i < 16; i++) {
            float4 kv4 = kr[i];
            acc += kv4.x*sm_q[i*4+0] + kv4.y*sm_q[i*4+1]
                 + kv4.z*sm_q[i*4+2] + kv4.w*sm_q[i*4+3];
        }
        sm_attn[s] = acc;
    }
    __syncthreads();

    /* 17 softmax variants, warp-per-variant (16 warps); zero pad tail */
    for (int var = warp; var < 17; var += 16) {
        float* pr = sm_p + var * PROW;
        const float* mrow = (var < 16)
            ? (mask + (size_t)((b*NBOX + var)*NHEAD + h) * S_LEN) : (const float*)0;
        float mx = -3.0e38f;
        for (int s = lane; s < S_LEN; s += 32) {
            float a = sm_attn[s] + (mrow ? __ldg(mrow + s) : 0.0f);
            pr[s] = a;
            mx = fmaxf(mx, a);
        }
        #pragma unroll
        for (int o = 16; o; o >>= 1)
            mx = fmaxf(mx, __shfl_xor_sync(0xffffffffu, mx, o));
        float sum = 0.0f;
        for (int s = lane; s < S_LEN; s += 32) {
            float e = expf(pr[s] - mx);
            pr[s] = e;
            sum += e;
        }
        #pragma unroll
        for (int o = 16; o; o >>= 1)
            sum += __shfl_xor_sync(0xffffffffu, sum, o);
        float inv = 1.0f / sum;
        for (int s = lane; s < S_LEN; s += 32) pr[s] *= inv;
        /* zero the padded tail [577,608) */
        if (lane < PROW - S_LEN) pr[S_LEN + lane] = 0.0f;
    }
    __syncthreads();

    /* P @ V: thread (e, rg) handles contiguous s in [rg*76, rg*76+76) */
    {
        int e = t & 63, rg = t >> 6;       // rg uniform per warp
        const float* vcol = g_kv + 1024 + h*HD + e;
        int sbase = rg * CHUNK;
        float acc[17];
        #pragma unroll
        for (int v = 0; v < 17; v++) acc[v] = 0.0f;

        for (int i = 0; i < CHUNK; i += 4) {
            int s = sbase + i;
            float4 vv;
            vv.x = (s+0 < S_LEN) ? vcol[(size_t)((s+0)*BATCH + b)*2048] : 0.0f;
            vv.y = (s+1 < S_LEN) ? vcol[(size_t)((s+1)*BATCH + b)*2048] : 0.0f;
            vv.z = (s+2 < S_LEN) ? vcol[(size_t)((s+2)*BATCH + b)*2048] : 0.0f;
            vv.w = (s+3 < S_LEN) ? vcol[(size_t)((s+3)*BATCH + b)*2048] : 0.0f;
            #pragma unroll
            for (int v = 0; v < 17; v++) {
                float4 p4 = *(const float4*)&sm_p[v*PROW + s];
                acc[v] += p4.x*vv.x + p4.y*vv.y + p4.z*vv.z + p4.w*vv.w;
            }
        }
        #pragma unroll
        for (int v = 0; v < 17; v++)
            sm_part[rg*1088 + v*64 + e] = acc[v];
    }
    __syncthreads();

    /* reduce 8 rg-partials -> 17*64 outputs */
    for (int o = t; o < 1088; o += 512) {
        int var = o >> 6, e2 = o & 63;
        float s = 0.0f;
        #pragma unroll
        for (int rg = 0; rg < 8; rg++) s += sm_part[rg*1088 + o];
        int col = h*HD + e2;
        if (var < 16)
            g_attout[(size_t)(b*NBOX + var)*DIM + col] = f2tf32f(s);
        else
            g_attout[(size_t)(128 + b)*DIM + col] = f2tf32f(s);
    }
}

/* ------------------------------------------------------------------ */
__global__ void gelu_reduce_kernel(const float* __restrict__ fb) {
    int i = blockIdx.x * blockDim.x + threadIdx.x;
    if (i >= MROW*4096/4) return;
    int n4 = i & (4096/4 - 1);
    float4 bv = ((const float4*)fb)[n4];
    float v[4] = {bv.x, bv.y, bv.z, bv.w};
    #pragma unroll
    for (int z = 0; z < 4; z++) {
        float4 p = ((const float4*)g_part)[(size_t)z*(MROW*4096/4) + i];
        v[0] += p.x; v[1] += p.y; v[2] += p.z; v[3] += p.w;
    }
    float4 o;
    #pragma unroll
    for (int j = 0; j < 4; j++)
        v[j] = f2tf32f(v[j] / (1.0f + expf(-1.702f * v[j])));
    o.x = v[0]; o.y = v[1]; o.z = v[2]; o.w = v[3];
    ((float4*)g_fc)[i] = o;
}

/* ------------------------------------------------------------------ */
__global__ void resid_ln2_kernel(const float* __restrict__ x,
                                 const float* __restrict__ ob,
                                 const float* __restrict__ g2,
                                 const float* __restrict__ b2) {
    __shared__ float sred[32];
    int m = blockIdx.x, t = threadIdx.x;
    int b = (m < 128) ? (m >> 4) : (m - 128);
    float4 xv = ((const float4*)(x + (size_t)b*DIM))[t];
    float4 bo = ((const float4*)ob)[t];
    float rx = xv.x + bo.x, ry = xv.y + bo.y, rz = xv.z + bo.z, rw = xv.w + bo.w;
    #pragma unroll
    for (int z = 0; z < 8; z++) {
        float4 p = ((const float4*)(g_part + (size_t)(z*MROW + m)*DIM))[t];
        rx += p.x; ry += p.y; rz += p.z; rw += p.w;
    }
    float4 r = make_float4(rx, ry, rz, rw);
    ((float4*)(g_resid + (size_t)m*DIM))[t] = r;
    float s = r.x + r.y + r.z + r.w;
    s = block_reduce(s, sred, false);
    float mean = s * (1.0f/DIM);
    float dx = r.x-mean, dy = r.y-mean, dz = r.z-mean, dw = r.w-mean;
    float ss = dx*dx + dy*dy + dz*dz + dw*dw;
    ss = block_reduce(ss, sred, false);
    float inv = rsqrtf(ss*(1.0f/DIM) + 1e-5f);
    float4 gv = ((const float4*)g2)[t];
    float4 bv = ((const float4*)b2)[t];
    float4 o;
    o.x = f2tf32f(dx*inv*gv.x + bv.x);  o.y = f2tf32f(dy*inv*gv.y + bv.y);
    o.z = f2tf32f(dz*inv*gv.z + bv.z);  o.w = f2tf32f(dw*inv*gv.w + bv.w);
    ((float4*)(g_t + (size_t)m*DIM))[t] = o;
}

/* ------------------------------------------------------------------ */
__global__ void final_kernel(const float* __restrict__ pb, float* __restrict__ out) {
    int m = blockIdx.x, t = threadIdx.x;
    float4 r  = ((const float4*)(g_resid + (size_t)m*DIM))[t];
    float4 bv = ((const float4*)pb)[t];
    float ox = r.x + bv.x, oy = r.y + bv.y, oz = r.z + bv.z, ow = r.w + bv.w;
    #pragma unroll
    for (int z = 0; z < 16; z++) {
        float4 p = ((const float4*)(g_part + (size_t)(z*MROW + m)*DIM))[t];
        ox += p.x; oy += p.y; oz += p.z; ow += p.w;
    }
    float4 o = make_float4(ox, oy, oz, ow);
    float* dst = (m < 128) ? (out + (size_t)m*DIM)
                           : (out + 128*DIM + (size_t)(m-128)*DIM);
    ((float4*)dst)[t] = o;
}

/* ------------------------------------------------------------------ */
extern "C" void kernel_launch(void* const* d_in, const int* in_sizes, int n_in,
                              void* d_out, int out_size) {
    const float* x         = (const float*)d_in[0];
    const float* mask      = (const float*)d_in[1];
    const float* in_proj_w = (const float*)d_in[5];
    const float* in_proj_b = (const float*)d_in[6];
    const float* out_w     = (const float*)d_in[7];
    const float* out_b     = (const float*)d_in[8];
    const float* ln1_g     = (const float*)d_in[9];
    const float* ln1_b     = (const float*)d_in[10];
    const float* ln2_g     = (const float*)d_in[11];
    const float* ln2_b     = (const float*)d_in[12];
    const float* fc_w      = (const float*)d_in[13];
    const float* fc_b      = (const float*)d_in[14];
    const float* proj_w    = (const float*)d_in[15];
    const float* proj_b    = (const float*)d_in[16];

    float *ph, *pkv, *pattout, *pt, *pfc, *ppart;
    cudaGetSymbolAddress((void**)&ph,      g_h);
    cudaGetSymbolAddress((void**)&pkv,     g_kv);
    cudaGetSymbolAddress((void**)&pattout, g_attout);
    cudaGetSymbolAddress((void**)&pt,      g_t);
    cudaGetSymbolAddress((void**)&pfc,     g_fc);
    cudaGetSymbolAddress((void**)&ppart,   g_part);

    cudaFuncSetAttribute(gemm_w64<0,0,1>,  cudaFuncAttributeMaxDynamicSharedMemorySize, GEMM_SMEM);
    cudaFuncSetAttribute(gemm_w64<0,0,4>,  cudaFuncAttributeMaxDynamicSharedMemorySize, GEMM_SMEM);
    cudaFuncSetAttribute(gemm_w64<0,0,8>,  cudaFuncAttributeMaxDynamicSharedMemorySize, GEMM_SMEM);
    cudaFuncSetAttribute(gemm_w64<0,0,16>, cudaFuncAttributeMaxDynamicSharedMemorySize, GEMM_SMEM);
    cudaFuncSetAttribute(fused_attn_kernel, cudaFuncAttributeMaxDynamicSharedMemorySize, ATT_SMEM);

    /* 1. LN1 over all tokens (tf32-rounded out) */
    ln1_kernel<<<NROWS, 256>>>(x, ln1_g, ln1_b, ph);

    /* 2. K,V projection: [4616,1024] x [2048,1024]^T (tf32 path) */
    gemm_w64<0,0,1><<<dim3(2048/128, (NROWS+127)/128), 128, GEMM_SMEM>>>(
        ph, in_proj_w + 1024*1024, in_proj_b + 1024, pkv, NROWS, 2048, 1024);

    /* 3. fused q proj + attn + softmax + P@V (vectorized p loads) */
    fused_attn_kernel<<<BATCH*NHEAD, 512, ATT_SMEM>>>(mask, in_proj_w, in_proj_b);

    /* 4. output projection, split-K 8 (128 CTAs) */
    gemm_w64<0,0,8><<<dim3(1024/128, 2, 8), 128, GEMM_SMEM>>>(
        pattout, out_w, out_b, ppart, MROW, 1024, 1024);

    /* 5. residual + out_b + LN2 (reduces 8 partials) */
    resid_ln2_kernel<<<MROW, 256>>>(x, out_b, ln2_g, ln2_b);

    /* 6. MLP fc, split-K 4 (256 CTAs) */
    gemm_w64<0,0,4><<<dim3(4096/128, 2, 4), 128, GEMM_SMEM>>>(
        pt, fc_w, fc_b, ppart, MROW, 4096, 1024);

    /* 7. reduce 4 partials + bias + QuickGELU */
    gelu_reduce_kernel<<<(MROW*4096/4 + 255)/256, 256>>>(fc_b);

    /* 8. MLP proj, split-K 16 (256 CTAs) */
    gemm_w64<0,0,16><<<dim3(1024/128, 2, 16), 128, GEMM_SMEM>>>(
        pfc, proj_w, proj_b, ppart, MROW, 1024, 4096);

    /* 9. residual + proj_b + scatter (reduces 16 partials) */
    final_kernel<<<MROW, 256>>>(proj_b, (float*)d_out);
}